// round 15
// baseline (speedup 1.0000x reference)
#include <cuda_runtime.h>
#include <cuda_bf16.h>
#include <cstdint>

#define B_  8
#define C_  64
#define H_  128
#define W_  128
#define OC_ 128
#define HP_ 130

#define NSM 152
#define ROWB 16640                        // slab: 130 px * 64 ch * 2 B
#define TAPB 16384                        // one tap of W
#define SE_OFF   (9 * TAPB)               // 147456: E ring (4 slabs)
#define PART_OFF (SE_OFF + 4 * ROWB)      // 214016: P[4][132] f32
#define RZ_OFF   (PART_OFF + 4 * 132 * 4) // 216128: rz (128 floats)
#define CONV_SMEM (RZ_OFF + 512)          // 216640

// ---------------------------------------------------------------------------
__device__ __forceinline__ uint32_t smem_u32(const void* p) {
    uint32_t a;
    asm("{ .reg .u64 t; cvta.to.shared.u64 t, %1; cvt.u32.u64 %0, t; }" : "=r"(a) : "l"(p));
    return a;
}
#define LDSM_X4(r0, r1, r2, r3, addr) \
    asm volatile("ldmatrix.sync.aligned.m8n8.x4.shared.b16 {%0,%1,%2,%3}, [%4];" \
        : "=r"(r0), "=r"(r1), "=r"(r2), "=r"(r3) : "r"(addr))

__device__ __forceinline__ void mma16816(float* c, const uint32_t* a,
                                         uint32_t b0, uint32_t b1) {
    asm volatile(
        "mma.sync.aligned.m16n8k16.row.col.f32.bf16.bf16.f32 "
        "{%0,%1,%2,%3}, {%4,%5,%6,%7}, {%8,%9}, {%0,%1,%2,%3};"
        : "+f"(c[0]), "+f"(c[1]), "+f"(c[2]), "+f"(c[3])
        : "r"(a[0]), "r"(a[1]), "r"(a[2]), "r"(a[3]), "r"(b0), "r"(b1));
}

// ---------------------------------------------------------------------------
// Warp-specialized fused persistent kernel:
//   warps 0-7  : R9 MMA consumer (code untouched)
//   warps 8-9  : E producer (LDG + expf + swizzled STS.128 + channel sums)
// One kernel, zero E DRAM traffic, 2 barriers/row.
// ---------------------------------------------------------------------------
__global__ void __launch_bounds__(320) conv_fused_kernel(
    const float* __restrict__ x, const float* __restrict__ mem,
    float* __restrict__ out) {
    extern __shared__ __align__(128) char smem[];
    const uint32_t sbase = smem_u32(smem);
    const int tid = threadIdx.x;
    const int wid = tid >> 5, lane = tid & 31;
    const int wm = wid & 1, wn = (wid >> 1) & 3;   // consumer 2 x 4 warp grid

    const int r0 = (int)(((long)blockIdx.x * (B_ * H_)) / NSM);
    const int r1 = (int)(((long)(blockIdx.x + 1) * (B_ * H_)) / NSM);

    float* Pring = reinterpret_cast<float*>(smem + PART_OFF);  // [4][132]
    float* rzbuf = reinterpret_cast<float*>(smem + RZ_OFF);    // [128]

    // ---- W prep (all 320 threads): mem[k][oc] -> Wsm[tap][oc][c] swizzled
    {
        const float4* m4 = reinterpret_cast<const float4*>(mem);
#pragma unroll 1
        for (int i = tid; i < 18432; i += 320) {
            float4 v = m4[i];
            int k = i >> 5, oc0 = (i & 31) * 4;
            int c = k / 9, tap = k - 9 * c;
            char* tb = smem + tap * TAPB;
            float vv[4] = {v.x, v.y, v.z, v.w};
#pragma unroll
            for (int q = 0; q < 4; q++) {
                uint32_t off  = (uint32_t)(oc0 + q) * 128 + c * 2;
                uint32_t soff = off ^ ((off >> 3) & 0x70);
                *reinterpret_cast<__nv_bfloat16*>(tb + soff) = __float2bfloat16(vv[q]);
            }
        }
    }

    // ---- producer helpers ----
    auto produce_pixel = [&](int bb, int hp, int pw) {   // pw in 1..128
        const int slot = hp & 3;
        char* sl = smem + SE_OFF + slot * ROWB;
        const float* xp = x + ((size_t)bb * C_ * H_ + (size_t)(hp - 1)) * W_ + (pw - 1);
        float s = 0.f;
#pragma unroll
        for (int q = 0; q < 8; q++) {
            float e[8];
#pragma unroll
            for (int cc = 0; cc < 8; cc++)
                e[cc] = xp[(size_t)(q * 8 + cc) * (H_ * W_)];
            uint32_t pk[4];
#pragma unroll
            for (int cc = 0; cc < 8; cc += 2) {
                float e0 = __expf(e[cc]), e1 = __expf(e[cc + 1]);
                s += e0 + e1;
                __nv_bfloat162 v = __floats2bfloat162_rn(e0, e1);
                pk[cc >> 1] = *reinterpret_cast<const uint32_t*>(&v);
            }
            uint32_t off  = (uint32_t)pw * 128 + q * 16;
            uint32_t soff = off ^ ((off >> 3) & 0x70);
            *reinterpret_cast<uint4*>(sl + soff) = make_uint4(pk[0], pk[1], pk[2], pk[3]);
        }
        Pring[slot * 132 + pw] = s;
    };
    auto slab_border = [&](int hp, int t, int nt) {      // hp == 0 or HP_-1
        const int slot = hp & 3;
        char* sl = smem + SE_OFF + slot * ROWB;
        uint4 ones = make_uint4(0x3F803F80u, 0x3F803F80u, 0x3F803F80u, 0x3F803F80u);
        for (int i = t; i < ROWB / 16; i += nt)
            reinterpret_cast<uint4*>(sl)[i] = ones;
        for (int i = t; i < 130; i += nt) Pring[slot * 132 + i] = 64.f;
    };
    auto interior_edges = [&](int hp, int t) {           // wp = 0 / 129 columns
        const int slot = hp & 3;
        char* sl = smem + SE_OFF + slot * ROWB;
        if (t < 16) {
            int g = t & 7, wsel = t >> 3;
            uint32_t off  = (uint32_t)(wsel ? 129 * 128 : 0) + g * 16;
            uint32_t soff = off ^ ((off >> 3) & 0x70);
            *reinterpret_cast<uint4*>(sl + soff) =
                make_uint4(0x3F803F80u, 0x3F803F80u, 0x3F803F80u, 0x3F803F80u);
        }
        if (t == 16) Pring[slot * 132 + 0]   = 64.f;
        if (t == 17) Pring[slot * 132 + 129] = 64.f;
    };

    // ---- consumer ldmatrix addressing constants ----
    int aRow[4], aSw[4];
#pragma unroll
    for (int mi = 0; mi < 4; mi++) {
        int row = wm * 64 + mi * 16 + (lane & 15);
        aRow[mi] = row * 128;
        aSw[mi]  = (row & 7) * 16;
    }
    const int aCol = (lane >> 4) << 4;
    int bRowBase[2];
#pragma unroll
    for (int nb = 0; nb < 2; nb++)
        bRowBase[nb] = wn * 32 + nb * 16 + ((lane >> 4) << 3) + (lane & 7);
    const int bCol = ((lane >> 3) & 1) << 4;
    const int ocB  = wm * 64 + (lane >> 2);
    const int wB   = wn * 32 + (lane & 3) * 2;

    int r = r0;
#pragma unroll 1
    while (r < r1) {
        const int bb = r >> 7;
        const int seg_end = min(r1, (bb + 1) << 7);

        {   // bootstrap: first 3 slabs (all 320 threads)
            const int h0 = r & 127;
#pragma unroll 1
            for (int qq = 0; qq < 3; qq++) {
                int hp = h0 + qq;
                if (hp == 0 || hp == HP_ - 1) slab_border(hp, tid, 320);
                else {
#pragma unroll 1
                    for (int idx = tid; idx < 128; idx += 320)
                        produce_pixel(bb, hp, 1 + idx);
                    interior_edges(hp, tid);
                }
            }
        }
        __syncthreads();

#pragma unroll 1
        for (int i = r; i < seg_end; i++) {
            const int h = i & 127;
            float acc[4][4][4];

            if (tid < 256) {
                // ---- consumer: rz then MMA (R9 code verbatim) ----
                if (tid < 128) {
                    float s = 0.f;
#pragma unroll
                    for (int ii = 0; ii < 3; ii++) {
                        const float* P = Pring + ((h + ii) & 3) * 132;
#pragma unroll
                        for (int j = 0; j < 3; j++) s += P[tid + j];
                    }
                    rzbuf[tid] = 1.0f / s;
                }
#pragma unroll
                for (int a0 = 0; a0 < 4; a0++)
#pragma unroll
                    for (int a1 = 0; a1 < 4; a1++)
#pragma unroll
                        for (int a2 = 0; a2 < 4; a2++) acc[a0][a1][a2] = 0.f;

#pragma unroll
                for (int t = 0; t < 9; t++) {
                    const int kh = t / 3, kw = t - 3 * kh;
                    const uint32_t sA = sbase + t * TAPB;
                    const uint32_t sE = sbase + SE_OFF + ((h + kh) & 3) * ROWB;
#pragma unroll
                    for (int ks = 0; ks < 4; ks++) {
                        uint32_t af[4][4];
#pragma unroll
                        for (int mi = 0; mi < 4; mi++) {
                            uint32_t addr = sA + aRow[mi] + ((ks * 32 + aCol) ^ aSw[mi]);
                            LDSM_X4(af[mi][0], af[mi][1], af[mi][2], af[mi][3], addr);
                        }
                        uint32_t bf[2][4];
#pragma unroll
                        for (int nb = 0; nb < 2; nb++) {
                            int row = bRowBase[nb] + kw;
                            uint32_t addr = sE + row * 128 +
                                            ((ks * 32 + bCol) ^ ((row & 7) * 16));
                            LDSM_X4(bf[nb][0], bf[nb][1], bf[nb][2], bf[nb][3], addr);
                        }
#pragma unroll
                        for (int mi = 0; mi < 4; mi++)
#pragma unroll
                            for (int ni = 0; ni < 4; ni++) {
                                uint32_t b0 = bf[ni >> 1][(ni & 1) * 2];
                                uint32_t b1 = bf[ni >> 1][(ni & 1) * 2 + 1];
                                mma16816(acc[mi][ni], af[mi], b0, b1);
                            }
                    }
                }
            } else {
                // ---- producer warps: slab h+3 for the next row ----
                const int p = tid - 256;
                if (i + 1 < seg_end) {
                    const int hpn = h + 3;
                    if (hpn == HP_ - 1) slab_border(hpn, p, 64);
                    else {
                        produce_pixel(bb, hpn, 1 + p);
                        produce_pixel(bb, hpn, 65 + p);
                        interior_edges(hpn, p);
                    }
                }
            }
            __syncthreads();

            if (tid < 256) {
                // ---- epilogue: scale + store ----
#pragma unroll
                for (int mi = 0; mi < 4; mi++)
#pragma unroll
                    for (int ni = 0; ni < 4; ni++) {
                        int oc = ocB + mi * 16;
                        int w  = wB + ni * 8;
                        float z0 = rzbuf[w], z1 = rzbuf[w + 1];
                        float* p0 = out + (((size_t)bb * OC_ + oc) * H_ + h) * W_ + w;
                        float2 v0 = make_float2(acc[mi][ni][0] * z0,
                                                acc[mi][ni][1] * z1);
                        float2 v1 = make_float2(acc[mi][ni][2] * z0,
                                                acc[mi][ni][3] * z1);
                        *reinterpret_cast<float2*>(p0) = v0;
                        *reinterpret_cast<float2*>(p0 + (size_t)8 * H_ * W_) = v1;
                    }
            }
        }
        r = seg_end;
    }
}

// ---------------------------------------------------------------------------
extern "C" void kernel_launch(void* const* d_in, const int* in_sizes, int n_in,
                              void* d_out, int out_size) {
    const float* x   = (const float*)d_in[0];   // [8,64,128,128]
    const float* mem = (const float*)d_in[1];   // [576,128]
    float* out = (float*)d_out;                 // [8,128,128,128]

    cudaFuncSetAttribute(conv_fused_kernel,
                         cudaFuncAttributeMaxDynamicSharedMemorySize, CONV_SMEM);

    conv_fused_kernel<<<NSM, 320, CONV_SMEM>>>(x, mem, out);
}

// round 16
// speedup vs baseline: 1.4085x; 1.4085x over previous
#include <cuda_runtime.h>
#include <cuda_bf16.h>
#include <cstdint>

#define B_  8
#define C_  64
#define H_  128
#define W_  128
#define OC_ 128
#define HP_ 130
#define WP_ 130

#define NSM 152
#define ROWB 16640                   // one padded row slab: 130 px * 64 ch * 2 B
#define TAPB 16384                   // one tap of W
#define SE_OFF (9 * TAPB)            // 147456: E ring (4 slabs)
#define RZ_OFF (SE_OFF + 4 * ROWB)   // 214016: rz ping-pong (2 x 128 floats)
#define CONV_SMEM (RZ_OFF + 1024)    // 215040 <= 227KB max

// E transposed: [b][hp][wp][c] bf16, border ring = 1.0 (= exp(0))
__device__ __nv_bfloat16 g_Egt[(size_t)B_ * HP_ * WP_ * C_];  // ~17.3 MB
__device__ float         g_Cs[(size_t)B_ * HP_ * WP_];        // channel sums, ring = 64
__device__ __nv_bfloat16 g_Wr[9 * OC_ * C_];                  // [tap][oc][c]

// ---------------------------------------------------------------------------
__device__ __forceinline__ uint32_t smem_u32(const void* p) {
    uint32_t a;
    asm("{ .reg .u64 t; cvta.to.shared.u64 t, %1; cvt.u32.u64 %0, t; }" : "=r"(a) : "l"(p));
    return a;
}
#define CP_ASYNC16(sa, ga) \
    asm volatile("cp.async.cg.shared.global [%0], [%1], 16;" :: "r"(sa), "l"(ga) : "memory")
#define CP_COMMIT() asm volatile("cp.async.commit_group;" ::: "memory")
#define CP_WAIT(n)  asm volatile("cp.async.wait_group %0;" :: "n"(n) : "memory")
#define LDSM_X4(r0, r1, r2, r3, addr) \
    asm volatile("ldmatrix.sync.aligned.m8n8.x4.shared.b16 {%0,%1,%2,%3}, [%4];" \
        : "=r"(r0), "=r"(r1), "=r"(r2), "=r"(r3) : "r"(addr))

__device__ __forceinline__ void mma16816(float* c, const uint32_t* a,
                                         uint32_t b0, uint32_t b1) {
    asm volatile(
        "mma.sync.aligned.m16n8k16.row.col.f32.bf16.bf16.f32 "
        "{%0,%1,%2,%3}, {%4,%5,%6,%7}, {%8,%9}, {%0,%1,%2,%3};"
        : "+f"(c[0]), "+f"(c[1]), "+f"(c[2]), "+f"(c[3])
        : "r"(a[0]), "r"(a[1]), "r"(a[2]), "r"(a[3]), "r"(b0), "r"(b1));
}

// ---------------------------------------------------------------------------
// Fused pre-kernel: blocks [0,2048): exp+transpose+chansum
//                   blocks [2048,..): weight rearrange + border ring
// ---------------------------------------------------------------------------
#define EXP_BLOCKS 2048
#define PREP_TOTAL (9 * OC_ * C_ + B_ * 516)
#define PRE_GRID   (EXP_BLOCKS + (PREP_TOTAL + 255) / 256)

__global__ __launch_bounds__(256) void pre_kernel(const float* __restrict__ x,
                                                  const float* __restrict__ mem) {
    const int bid = blockIdx.x;
    const int tid = threadIdx.x;

    if (bid >= EXP_BLOCKS) {
        int idx = (bid - EXP_BLOCKS) * 256 + tid;
        if (idx < 9 * OC_ * C_) {
            int c   = idx & 63;
            int oc  = (idx >> 6) & 127;
            int tap = idx >> 13;
            g_Wr[idx] = __float2bfloat16(mem[(c * 9 + tap) * OC_ + oc]);
            return;
        }
        idx -= 9 * OC_ * C_;
        if (idx >= B_ * 516) return;
        int b = idx / 516, p = idx % 516;
        int hp, wp;
        if (p < 260) { hp = (p < 130) ? 0 : (HP_ - 1); wp = p % 130; }
        else { int q = p - 260; hp = 1 + (q & 127); wp = (q < 128) ? 0 : (WP_ - 1); }
        size_t pix = ((size_t)b * HP_ + hp) * WP_ + wp;
        uint4 ones = make_uint4(0x3F803F80u, 0x3F803F80u, 0x3F803F80u, 0x3F803F80u);
        uint4* dst = reinterpret_cast<uint4*>(g_Egt + pix * C_);
#pragma unroll
        for (int i = 0; i < 8; i++) dst[i] = ones;
        g_Cs[pix] = 64.0f;
        return;
    }

    __shared__ float sm[C_][65];
    const int w0 = (bid & 1) * 64;
    const int h  = (bid >> 1) & 127;
    const int b  = bid >> 8;
    const int px = tid & 63, cq = tid >> 6;

    const float* xb = x + (((size_t)b * C_) * H_ + h) * W_ + w0 + px;
#pragma unroll
    for (int it = 0; it < 16; it++) {
        int c = it * 4 + cq;
        sm[c][px] = __expf(xb[(size_t)c * H_ * W_]);
    }
    __syncthreads();

    if (tid < 64) {
        float s = 0.f;
#pragma unroll
        for (int c = 0; c < C_; c++) s += sm[c][tid];
        g_Cs[((size_t)b * HP_ + h + 1) * WP_ + (w0 + tid + 1)] = s;
    }

    const int seg = tid & 7, r0 = tid >> 3;
#pragma unroll
    for (int pass = 0; pass < 2; pass++) {
        int r = pass * 32 + r0;
        uint32_t pk[4];
#pragma unroll
        for (int j = 0; j < 4; j++) {
            __nv_bfloat162 v = __floats2bfloat162_rn(sm[seg * 8 + 2 * j][r],
                                                     sm[seg * 8 + 2 * j + 1][r]);
            pk[j] = *reinterpret_cast<uint32_t*>(&v);
        }
        size_t pix = ((size_t)b * HP_ + h + 1) * WP_ + (w0 + r + 1);
        reinterpret_cast<uint4*>(g_Egt + pix * C_)[seg] = make_uint4(pk[0], pk[1], pk[2], pk[3]);
    }
}

// ---------------------------------------------------------------------------
// Persistent-strip conv, 512 threads / 16 warps (4 per SMSP).
// Warp grid 4M x 4N, warp tile 32oc x 32px. W resident; E 4-slot ring;
// 1 barrier per row (R9 schedule).
// ---------------------------------------------------------------------------
__global__ void __launch_bounds__(512) conv_mma_kernel(float* __restrict__ out) {
    extern __shared__ __align__(128) char smem[];
    const uint32_t sbase = smem_u32(smem);
    const int tid  = threadIdx.x;
    const int wid  = tid >> 5, lane = tid & 31;
    const int wm = wid & 3, wn = wid >> 2;    // 4 x 4 warp grid

    const int r0 = (int)(((long)blockIdx.x * (B_ * H_)) / NSM);
    const int r1 = (int)(((long)(blockIdx.x + 1) * (B_ * H_)) / NSM);

    float* rzbuf = reinterpret_cast<float*>(smem + RZ_OFF);

    // ---- prologue: all 9 W taps (147456 B contiguous) ----
    {
        const char* srcW = reinterpret_cast<const char*>(g_Wr);
        for (int i = tid; i < 9216; i += 512) {
            int off  = i * 16;
            int soff = off ^ ((off >> 3) & 0x70);
            CP_ASYNC16(sbase + soff, srcW + off);
        }
        CP_COMMIT();
    }

    auto issue_slab = [&](const char* EgB, int hp) {
        const char* src = EgB + (size_t)hp * ROWB;
        uint32_t dst = sbase + SE_OFF + (hp & 3) * ROWB;
        for (int i = tid; i < 1040; i += 512) {
            int off  = i * 16;
            int soff = off ^ ((off >> 3) & 0x70);
            CP_ASYNC16(dst + soff, src + off);
        }
    };
    auto write_rz = [&](int row) {
        if (tid < 128) {
            int b = row >> 7, h = row & 127;
            const float* Cb = g_Cs + ((size_t)b * HP_ + h) * WP_ + tid;
            float s = 0.f;
#pragma unroll
            for (int i = 0; i < 3; i++)
#pragma unroll
                for (int j = 0; j < 3; j++) s += Cb[i * WP_ + j];
            rzbuf[(row & 1) * 128 + tid] = 1.0f / s;
        }
    };

    // Per-warp ldmatrix addressing constants (32oc x 32px warp tile)
    int aRow[2], aSw[2];
#pragma unroll
    for (int mi = 0; mi < 2; mi++) {
        int row = wm * 32 + mi * 16 + (lane & 15);
        aRow[mi] = row * 128;
        aSw[mi]  = (row & 7) * 16;
    }
    const int aCol = (lane >> 4) << 4;
    int bRowBase[2];
#pragma unroll
    for (int nb = 0; nb < 2; nb++)
        bRowBase[nb] = wn * 32 + nb * 16 + ((lane >> 4) << 3) + (lane & 7);
    const int bCol = ((lane >> 3) & 1) << 4;
    const int ocB  = wm * 32 + (lane >> 2);
    const int wB   = wn * 32 + (lane & 3) * 2;

    int r = r0;
#pragma unroll 1
    while (r < r1) {
        const int bb = r >> 7;
        const char* EgB = reinterpret_cast<const char*>(g_Egt) +
                          (size_t)bb * HP_ * WP_ * C_ * 2;
        const int seg_end = min(r1, (bb + 1) << 7);

        // segment start: 3 slabs for first row + rz for first row
        {
            int h = r & 127;
            issue_slab(EgB, h);
            issue_slab(EgB, h + 1);
            issue_slab(EgB, h + 2);
            CP_COMMIT();
            write_rz(r);
            CP_WAIT(0);
            __syncthreads();
        }

#pragma unroll 1
        for (int i = r; i < seg_end; i++) {
            const int h = i & 127;
            if (i + 1 < seg_end) { issue_slab(EgB, h + 3); CP_COMMIT(); }
            if (i + 1 < r1) write_rz(i + 1);

            float acc[2][4][4];
#pragma unroll
            for (int a0 = 0; a0 < 2; a0++)
#pragma unroll
                for (int a1 = 0; a1 < 4; a1++)
#pragma unroll
                    for (int a2 = 0; a2 < 4; a2++) acc[a0][a1][a2] = 0.f;

#pragma unroll
            for (int t = 0; t < 9; t++) {
                const int kh = t / 3, kw = t - 3 * kh;
                const uint32_t sA = sbase + t * TAPB;
                const uint32_t sE = sbase + SE_OFF + ((h + kh) & 3) * ROWB;

#pragma unroll
                for (int ks = 0; ks < 4; ks++) {
                    uint32_t a[2][4];
#pragma unroll
                    for (int mi = 0; mi < 2; mi++) {
                        uint32_t addr = sA + aRow[mi] + ((ks * 32 + aCol) ^ aSw[mi]);
                        LDSM_X4(a[mi][0], a[mi][1], a[mi][2], a[mi][3], addr);
                    }
                    uint32_t bf[2][4];
#pragma unroll
                    for (int nb = 0; nb < 2; nb++) {
                        int row = bRowBase[nb] + kw;
                        uint32_t addr = sE + row * 128 +
                                        ((ks * 32 + bCol) ^ ((row & 7) * 16));
                        LDSM_X4(bf[nb][0], bf[nb][1], bf[nb][2], bf[nb][3], addr);
                    }
#pragma unroll
                    for (int mi = 0; mi < 2; mi++)
#pragma unroll
                        for (int ni = 0; ni < 4; ni++) {
                            uint32_t b0 = bf[ni >> 1][(ni & 1) * 2];
                            uint32_t b1 = bf[ni >> 1][(ni & 1) * 2 + 1];
                            mma16816(acc[mi][ni], a[mi], b0, b1);
                        }
                }
            }

            // ---- epilogue: scale + store ----
            const float* rz = rzbuf + (i & 1) * 128;
#pragma unroll
            for (int mi = 0; mi < 2; mi++)
#pragma unroll
                for (int ni = 0; ni < 4; ni++) {
                    int oc = ocB + mi * 16;
                    int w  = wB + ni * 8;
                    float z0 = rz[w], z1 = rz[w + 1];
                    float* p0 = out + (((size_t)bb * OC_ + oc) * H_ + h) * W_ + w;
                    float2 v0 = make_float2(acc[mi][ni][0] * z0, acc[mi][ni][1] * z1);
                    float2 v1 = make_float2(acc[mi][ni][2] * z0, acc[mi][ni][3] * z1);
                    *reinterpret_cast<float2*>(p0) = v0;
                    *reinterpret_cast<float2*>(p0 + (size_t)8 * H_ * W_) = v1;
                }

            CP_WAIT(0);
            __syncthreads();
        }
        r = seg_end;
    }
}

// ---------------------------------------------------------------------------
extern "C" void kernel_launch(void* const* d_in, const int* in_sizes, int n_in,
                              void* d_out, int out_size) {
    const float* x   = (const float*)d_in[0];   // [8,64,128,128]
    const float* mem = (const float*)d_in[1];   // [576,128]
    float* out = (float*)d_out;                 // [8,128,128,128]

    cudaFuncSetAttribute(conv_mma_kernel,
                         cudaFuncAttributeMaxDynamicSharedMemorySize, CONV_SMEM);

    pre_kernel<<<PRE_GRID, 256>>>(x, mem);
    conv_mma_kernel<<<NSM, 512, CONV_SMEM>>>(out);
}

// round 17
// speedup vs baseline: 1.4263x; 1.0127x over previous
#include <cuda_runtime.h>
#include <cuda_bf16.h>
#include <cstdint>

#define B_  8
#define C_  64
#define H_  128
#define W_  128
#define OC_ 128
#define HP_ 130
#define WP_ 130

#define NSM 152
#define ROWB 16640                    // one padded row slab: 130 px * 64 ch * 2 B
#define TAPB 16384                    // one tap of W
#define NRING 5
#define SE_OFF (9 * TAPB)             // 147456: E ring (5 slabs)
#define RZ_OFF (SE_OFF + NRING * ROWB)  // 230656: rz (2 x 128 floats)
#define CONV_SMEM (RZ_OFF + 1024)     // 231680 <= 232448 max

// E transposed: [b][hp][wp][c] bf16, border ring = 1.0 (= exp(0))
__device__ __nv_bfloat16 g_Egt[(size_t)B_ * HP_ * WP_ * C_];  // ~17.3 MB
__device__ float         g_Cs[(size_t)B_ * HP_ * WP_];        // channel sums, ring = 64
__device__ __nv_bfloat16 g_Wr[9 * OC_ * C_];                  // [tap][oc][c]

// ---------------------------------------------------------------------------
__device__ __forceinline__ uint32_t smem_u32(const void* p) {
    uint32_t a;
    asm("{ .reg .u64 t; cvta.to.shared.u64 t, %1; cvt.u32.u64 %0, t; }" : "=r"(a) : "l"(p));
    return a;
}
#define CP_ASYNC16(sa, ga) \
    asm volatile("cp.async.cg.shared.global [%0], [%1], 16;" :: "r"(sa), "l"(ga) : "memory")
#define CP_COMMIT() asm volatile("cp.async.commit_group;" ::: "memory")
#define CP_WAIT(n)  asm volatile("cp.async.wait_group %0;" :: "n"(n) : "memory")
#define LDSM_X4(r0, r1, r2, r3, addr) \
    asm volatile("ldmatrix.sync.aligned.m8n8.x4.shared.b16 {%0,%1,%2,%3}, [%4];" \
        : "=r"(r0), "=r"(r1), "=r"(r2), "=r"(r3) : "r"(addr))

__device__ __forceinline__ void mma16816(float* c, const uint32_t* a,
                                         uint32_t b0, uint32_t b1) {
    asm volatile(
        "mma.sync.aligned.m16n8k16.row.col.f32.bf16.bf16.f32 "
        "{%0,%1,%2,%3}, {%4,%5,%6,%7}, {%8,%9}, {%0,%1,%2,%3};"
        : "+f"(c[0]), "+f"(c[1]), "+f"(c[2]), "+f"(c[3])
        : "r"(a[0]), "r"(a[1]), "r"(a[2]), "r"(a[3]), "r"(b0), "r"(b1));
}

// ---------------------------------------------------------------------------
// Fused pre-kernel (unchanged): exp+transpose+chansum, W rearrange, borders
// ---------------------------------------------------------------------------
#define EXP_BLOCKS 2048
#define PREP_TOTAL (9 * OC_ * C_ + B_ * 516)
#define PRE_GRID   (EXP_BLOCKS + (PREP_TOTAL + 255) / 256)

__global__ __launch_bounds__(256) void pre_kernel(const float* __restrict__ x,
                                                  const float* __restrict__ mem) {
    const int bid = blockIdx.x;
    const int tid = threadIdx.x;

    if (bid >= EXP_BLOCKS) {
        int idx = (bid - EXP_BLOCKS) * 256 + tid;
        if (idx < 9 * OC_ * C_) {
            int c   = idx & 63;
            int oc  = (idx >> 6) & 127;
            int tap = idx >> 13;
            g_Wr[idx] = __float2bfloat16(mem[(c * 9 + tap) * OC_ + oc]);
            return;
        }
        idx -= 9 * OC_ * C_;
        if (idx >= B_ * 516) return;
        int b = idx / 516, p = idx % 516;
        int hp, wp;
        if (p < 260) { hp = (p < 130) ? 0 : (HP_ - 1); wp = p % 130; }
        else { int q = p - 260; hp = 1 + (q & 127); wp = (q < 128) ? 0 : (WP_ - 1); }
        size_t pix = ((size_t)b * HP_ + hp) * WP_ + wp;
        uint4 ones = make_uint4(0x3F803F80u, 0x3F803F80u, 0x3F803F80u, 0x3F803F80u);
        uint4* dst = reinterpret_cast<uint4*>(g_Egt + pix * C_);
#pragma unroll
        for (int i = 0; i < 8; i++) dst[i] = ones;
        g_Cs[pix] = 64.0f;
        return;
    }

    __shared__ float sm[C_][65];
    const int w0 = (bid & 1) * 64;
    const int h  = (bid >> 1) & 127;
    const int b  = bid >> 8;
    const int px = tid & 63, cq = tid >> 6;

    const float* xb = x + (((size_t)b * C_) * H_ + h) * W_ + w0 + px;
#pragma unroll
    for (int it = 0; it < 16; it++) {
        int c = it * 4 + cq;
        sm[c][px] = __expf(xb[(size_t)c * H_ * W_]);
    }
    __syncthreads();

    if (tid < 64) {
        float s = 0.f;
#pragma unroll
        for (int c = 0; c < C_; c++) s += sm[c][tid];
        g_Cs[((size_t)b * HP_ + h + 1) * WP_ + (w0 + tid + 1)] = s;
    }

    const int seg = tid & 7, r0 = tid >> 3;
#pragma unroll
    for (int pass = 0; pass < 2; pass++) {
        int r = pass * 32 + r0;
        uint32_t pk[4];
#pragma unroll
        for (int j = 0; j < 4; j++) {
            __nv_bfloat162 v = __floats2bfloat162_rn(sm[seg * 8 + 2 * j][r],
                                                     sm[seg * 8 + 2 * j + 1][r]);
            pk[j] = *reinterpret_cast<uint32_t*>(&v);
        }
        size_t pix = ((size_t)b * HP_ + h + 1) * WP_ + (w0 + r + 1);
        reinterpret_cast<uint4*>(g_Egt + pix * C_)[seg] = make_uint4(pk[0], pk[1], pk[2], pk[3]);
    }
}

// ---------------------------------------------------------------------------
// Persistent-strip conv: 512 thr / 16 warps, 2 rows per iteration.
// Warps 0-7 -> row h, warps 8-15 -> row h+1; each warp = R9's 64x32 tile.
// W resident; E in a 5-slot slab ring; 2 barriers per pair (1/row).
// ---------------------------------------------------------------------------
__global__ void __launch_bounds__(512) conv_mma_kernel(float* __restrict__ out) {
    extern __shared__ __align__(128) char smem[];
    const uint32_t sbase = smem_u32(smem);
    const int tid  = threadIdx.x;
    const int wid  = tid >> 5, lane = tid & 31;
    const int row_sel = wid >> 3;             // 0 or 1
    const int w8 = wid & 7;
    const int wm = w8 & 1, wn = w8 >> 1;      // 2 x 4 warp grid within row

    const int r0 = (int)(((long)blockIdx.x * (B_ * H_)) / NSM);
    const int r1 = (int)(((long)(blockIdx.x + 1) * (B_ * H_)) / NSM);

    float* rzbuf = reinterpret_cast<float*>(smem + RZ_OFF);   // [2][128]

    // ---- prologue: all 9 W taps ----
    {
        const char* srcW = reinterpret_cast<const char*>(g_Wr);
        for (int i = tid; i < 9216; i += 512) {
            int off  = i * 16;
            int soff = off ^ ((off >> 3) & 0x70);
            CP_ASYNC16(sbase + soff, srcW + off);
        }
        CP_COMMIT();
    }

    auto issue_slab = [&](const char* EgB, int hp) {
        const char* src = EgB + (size_t)hp * ROWB;
        uint32_t dst = sbase + SE_OFF + (hp % NRING) * ROWB;
        for (int i = tid; i < 1040; i += 512) {
            int off  = i * 16;
            int soff = off ^ ((off >> 3) & 0x70);
            CP_ASYNC16(dst + soff, src + off);
        }
    };
    auto write_rz = [&](int row, int half) {
        int lt = tid - half * 128;
        if (lt >= 0 && lt < 128) {
            int b = row >> 7, h = row & 127;
            const float* Cb = g_Cs + ((size_t)b * HP_ + h) * WP_ + lt;
            float s = 0.f;
#pragma unroll
            for (int i2 = 0; i2 < 3; i2++)
#pragma unroll
                for (int j = 0; j < 3; j++) s += Cb[i2 * WP_ + j];
            rzbuf[half * 128 + lt] = 1.0f / s;
        }
    };

    // Per-warp ldmatrix addressing (R9 64oc x 32px tile)
    int aRow[4], aSw[4];
#pragma unroll
    for (int mi = 0; mi < 4; mi++) {
        int row = wm * 64 + mi * 16 + (lane & 15);
        aRow[mi] = row * 128;
        aSw[mi]  = (row & 7) * 16;
    }
    const int aCol = (lane >> 4) << 4;
    int bRowBase[2];
#pragma unroll
    for (int nb = 0; nb < 2; nb++)
        bRowBase[nb] = wn * 32 + nb * 16 + ((lane >> 4) << 3) + (lane & 7);
    const int bCol = ((lane >> 3) & 1) << 4;
    const int ocB  = wm * 64 + (lane >> 2);
    const int wB   = wn * 32 + (lane & 3) * 2;

#define MMA_TAP(t_, hrow_)                                                     \
    do {                                                                       \
        const int kh_ = (t_) / 3, kw_ = (t_) - 3 * kh_;                        \
        const uint32_t sA_ = sbase + (t_) * TAPB;                              \
        const uint32_t sE_ = sbase + SE_OFF + (((hrow_) + kh_) % NRING) * ROWB;\
        _Pragma("unroll")                                                      \
        for (int ks = 0; ks < 4; ks++) {                                       \
            uint32_t af_[4][4];                                                \
            _Pragma("unroll")                                                  \
            for (int mi = 0; mi < 4; mi++) {                                   \
                uint32_t addr = sA_ + aRow[mi] + ((ks * 32 + aCol) ^ aSw[mi]); \
                LDSM_X4(af_[mi][0], af_[mi][1], af_[mi][2], af_[mi][3], addr); \
            }                                                                  \
            uint32_t bf_[2][4];                                                \
            _Pragma("unroll")                                                  \
            for (int nb = 0; nb < 2; nb++) {                                   \
                int row = bRowBase[nb] + kw_;                                  \
                uint32_t addr = sE_ + row * 128 +                              \
                                ((ks * 32 + bCol) ^ ((row & 7) * 16));         \
                LDSM_X4(bf_[nb][0], bf_[nb][1], bf_[nb][2], bf_[nb][3], addr); \
            }                                                                  \
            _Pragma("unroll")                                                  \
            for (int mi = 0; mi < 4; mi++)                                     \
                _Pragma("unroll")                                              \
                for (int ni = 0; ni < 4; ni++) {                               \
                    uint32_t b0 = bf_[ni >> 1][(ni & 1) * 2];                  \
                    uint32_t b1 = bf_[ni >> 1][(ni & 1) * 2 + 1];              \
                    mma16816(acc[mi][ni], af_[mi], b0, b1);                    \
                }                                                              \
        }                                                                      \
    } while (0)

#define EPILOGUE(hh_, rz_)                                                     \
    do {                                                                       \
        _Pragma("unroll")                                                      \
        for (int mi = 0; mi < 4; mi++)                                         \
            _Pragma("unroll")                                                  \
            for (int ni = 0; ni < 4; ni++) {                                   \
                int oc = ocB + mi * 16;                                        \
                int w  = wB + ni * 8;                                          \
                float z0 = (rz_)[w], z1 = (rz_)[w + 1];                        \
                float* p0 = out + (((size_t)bb * OC_ + oc) * H_ + (hh_)) * W_ + w; \
                float2 v0 = make_float2(acc[mi][ni][0] * z0, acc[mi][ni][1] * z1); \
                float2 v1 = make_float2(acc[mi][ni][2] * z0, acc[mi][ni][3] * z1); \
                *reinterpret_cast<float2*>(p0) = v0;                           \
                *reinterpret_cast<float2*>(p0 + (size_t)8 * H_ * W_) = v1;     \
            }                                                                  \
    } while (0)

    int r = r0;
#pragma unroll 1
    while (r < r1) {
        const int bb = r >> 7;
        const char* EgB = reinterpret_cast<const char*>(g_Egt) +
                          (size_t)bb * HP_ * WP_ * C_ * 2;
        const int seg_end = min(r1, (bb + 1) << 7);
        const int h0 = r & 127;

        // bootstrap: slabs for first pair (or tail)
        issue_slab(EgB, h0);
        issue_slab(EgB, h0 + 1);
        issue_slab(EgB, h0 + 2);
        if (seg_end - r >= 2) issue_slab(EgB, h0 + 3);
        CP_COMMIT();
        CP_WAIT(0);
        __syncthreads();

        // ---- pair loop ----
#pragma unroll 1
        while (r + 1 < seg_end) {
            const int h = r & 127;
            if (r + 2 < seg_end) { issue_slab(EgB, h + 4); CP_COMMIT(); }
            write_rz(r, 0);
            write_rz(r + 1, 1);

            float acc[4][4][4];
#pragma unroll
            for (int a0 = 0; a0 < 4; a0++)
#pragma unroll
                for (int a1 = 0; a1 < 4; a1++)
#pragma unroll
                    for (int a2 = 0; a2 < 4; a2++) acc[a0][a1][a2] = 0.f;

            const int hrow = h + row_sel;
#pragma unroll
            for (int t = 0; t < 3; t++) MMA_TAP(t, hrow);
            __syncthreads();   // kh=0 done: slab h free; rz visible
            if (r + 3 < seg_end) { issue_slab(EgB, h + 5); CP_COMMIT(); }
#pragma unroll
            for (int t = 3; t < 9; t++) MMA_TAP(t, hrow);

            EPILOGUE(h + row_sel, rzbuf + row_sel * 128);

            CP_WAIT(0);
            __syncthreads();
            r += 2;
        }

        // ---- single-row tail ----
        if (r < seg_end) {
            const int h = r & 127;
            write_rz(r, 0);
            __syncthreads();
            if (row_sel == 0) {
                float acc[4][4][4];
#pragma unroll
                for (int a0 = 0; a0 < 4; a0++)
#pragma unroll
                    for (int a1 = 0; a1 < 4; a1++)
#pragma unroll
                        for (int a2 = 0; a2 < 4; a2++) acc[a0][a1][a2] = 0.f;
#pragma unroll
                for (int t = 0; t < 9; t++) MMA_TAP(t, h);
                EPILOGUE(h, rzbuf);
            }
            __syncthreads();
            r += 1;
        }
    }
#undef MMA_TAP
#undef EPILOGUE
}

// ---------------------------------------------------------------------------
extern "C" void kernel_launch(void* const* d_in, const int* in_sizes, int n_in,
                              void* d_out, int out_size) {
    const float* x   = (const float*)d_in[0];   // [8,64,128,128]
    const float* mem = (const float*)d_in[1];   // [576,128]
    float* out = (float*)d_out;                 // [8,128,128,128]

    cudaFuncSetAttribute(conv_mma_kernel,
                         cudaFuncAttributeMaxDynamicSharedMemorySize, CONV_SMEM);

    pre_kernel<<<PRE_GRID, 256>>>(x, mem);
    conv_mma_kernel<<<NSM, 512, CONV_SMEM>>>(out);
}